// round 14
// baseline (speedup 1.0000x reference)
#include <cuda_runtime.h>

typedef unsigned long long u64;
typedef unsigned int u32;

#define HH 224
#define WW 224
#define IMG (HH * WW)
#define NPASS 9
#define W3MASK 0xFFFFFFFFull
#define FULLM 0xFFFFFFFFu

// bits 0..k-1 of word j (j*64 .. j*64+63) of a 224-bit mask
__device__ __forceinline__ u64 mask_lt(int k, int j) {
    int lo = j * 64;
    if (k <= lo) return 0ull;
    if (k >= lo + 64) return ~0ull;
    return (1ull << (k - lo)) - 1ull;
}

// first row e >= q such that row e-1 is a zero-b row (z-bit set); HH if none.
// q >= 1. Segment starting at e may be initialized with (p1,p2)=(0,0): exact
// (ab(e) = nn(e-1)&nn(e-2) = 0 since nn(e-1)=0; ab(e+1) = nn(e)&nn(e-1) = 0).
__device__ __forceinline__ int find_entry(const u32* zm, int q) {
    int pos = q - 1;
    int w = pos >> 5;
    u32 bits = zm[w] & (FULLM << (pos & 31));
    while (bits == 0) {
        if (++w >= 7) return HH;
        bits = zm[w];
    }
    int z = (w << 5) + __ffs(bits) - 1;
    return (z + 1 > HH) ? HH : z + 1;
}

__global__ __launch_bounds__(128) void mask_ca_kernel(const float* __restrict__ x,
                                                      float* __restrict__ out) {
    __shared__ u64 s_mask[HH][4];   // current mask (post rect-fill)
    __shared__ u64 s_b1[HH][4];     // base == exactly one of below/right
    __shared__ u64 s_b2[HH][4];     // base == both
    __shared__ u64 s_n[HH][4];      // serial-scan output (pre rect-fill), sparse via s_src
    __shared__ int s_src[HH];       // representative row: value of row r is s_n[s_src[r]]
    __shared__ u32 s_fmap[8];       // bit r: g(r-1)==g(r)==g(r+1) (=> b(r)==b(r-1))
    __shared__ u32 s_zmap[8];       // bit r: (b1|b2)==0 at row r (carry barrier!)
    __shared__ u64 s_wcm[4][4];     // per-warp column-OR of its rows
    __shared__ int s_whmin[4], s_whmax[4];
    __shared__ int s_chg[NPASS];    // write-once per pass (no reset race)

    const int tid  = threadIdx.x;
    const int lane = tid & 31;
    const int warp = tid >> 5;
    const float* xi = x + (size_t)blockIdx.x * IMG;
    float* oi = out + (size_t)blockIdx.x * IMG;

    // ---- pack input: threshold > 0.8, byte-wise, no ballots, deep MLP ----
    {
        unsigned char* sb = (unsigned char*)s_mask;
#pragma unroll 4
        for (int idx = tid; idx < HH * 32; idx += 128) {
            int r = idx >> 5, b = idx & 31;
            unsigned char v = 0;
            if (b < 28) {
                const float4* p = (const float4*)(xi + r * WW + b * 8);
                float4 a = p[0], c = p[1];
                v = (unsigned char)((a.x > 0.8f)
                  | ((a.y > 0.8f) << 1)
                  | ((a.z > 0.8f) << 2)
                  | ((a.w > 0.8f) << 3)
                  | ((c.x > 0.8f) << 4)
                  | ((c.y > 0.8f) << 5)
                  | ((c.z > 0.8f) << 6)
                  | ((c.w > 0.8f) << 7));
            }
            sb[idx] = v;
        }
    }
    if (tid == 0) {
#pragma unroll
        for (int p = 0; p < NPASS; p++) s_chg[p] = 0;
    }
    __syncthreads();

    // ---- initial b1/b2 + flag bitmaps from packed input ----
#define INIT_ROW(RR, FLOUT) do {                                               \
        const int r_ = (RR);                                                   \
        u64 g0 = s_mask[r_][0], g1 = s_mask[r_][1];                            \
        u64 g2 = s_mask[r_][2], g3 = s_mask[r_][3];                            \
        u64 n0, n1, n2, n3;                                                    \
        if (r_ < HH - 2) {                                                     \
            n0 = s_mask[r_ + 1][0]; n1 = s_mask[r_ + 1][1];                    \
            n2 = s_mask[r_ + 1][2]; n3 = s_mask[r_ + 1][3];                    \
        } else if (r_ == HH - 2) {                                             \
            n0 = ~0ull; n1 = ~0ull; n2 = ~0ull; n3 = W3MASK;                   \
        } else { n0 = n1 = n2 = n3 = 0ull; }                                   \
        u64 bl0 = g0 & n0, bl1 = g1 & n1, bl2 = g2 & n2, bl3 = g3 & n3;        \
        u64 rt0 = ((g0 >> 1) | (g1 << 63)) & g0;                               \
        u64 rt1 = ((g1 >> 1) | (g2 << 63)) & g1;                               \
        u64 rt2 = ((g2 >> 1) | (g3 << 63)) & g2;                               \
        u64 rt3 = ((g3 >> 1) | (1ull << 30)) & g3;                             \
        s_b1[r_][0] = bl0 ^ rt0; s_b1[r_][1] = bl1 ^ rt1;                      \
        s_b1[r_][2] = bl2 ^ rt2; s_b1[r_][3] = bl3 ^ rt3;                      \
        s_b2[r_][0] = bl0 & rt0; s_b2[r_][1] = bl1 & rt1;                      \
        s_b2[r_][2] = bl2 & rt2; s_b2[r_][3] = bl3 & rt3;                      \
        int fl_ = (((bl0 | rt0) | (bl1 | rt1) | (bl2 | rt2) | (bl3 | rt3))     \
                   == 0ull) ? 2 : 0;                                           \
        if (r_ >= 1 && r_ <= HH - 3) {                                         \
            u64 m0 = s_mask[r_ - 1][0], m1 = s_mask[r_ - 1][1];                \
            u64 m2 = s_mask[r_ - 1][2], m3 = s_mask[r_ - 1][3];                \
            u64 d = (m0 ^ g0) | (m1 ^ g1) | (m2 ^ g2) | (m3 ^ g3)              \
                  | (g0 ^ n0) | (g1 ^ n1) | (g2 ^ n2) | (g3 ^ n3);             \
            fl_ |= (d == 0ull) ? 1 : 0;                                        \
        }                                                                      \
        FLOUT = fl_;                                                           \
    } while (0)

    {
        int fl;
        INIT_ROW(tid, fl);
        u32 f1 = __ballot_sync(FULLM, fl & 1);
        u32 f2 = __ballot_sync(FULLM, fl & 2);
        if (lane == 0) { s_fmap[warp] = f1; s_zmap[warp] = f2; }
    }
    if (tid < 96) {
        int fl;
        INIT_ROW(128 + tid, fl);
        u32 f1 = __ballot_sync(FULLM, fl & 1);
        u32 f2 = __ballot_sync(FULLM, fl & 2);
        if (lane == 0) { s_fmap[4 + warp] = f1; s_zmap[4 + warp] = f2; }
    }
    __syncthreads();

    for (int pass = 0; pass < NPASS; pass++) {
        // ---- serial raster recurrence, 4 warps on disjoint segments ----
        {
            const int j = lane & 3;
            const bool loTest = (lane < 16);
            u32 fm[7], zm[7];
#pragma unroll
            for (int jj = 0; jj < 7; jj++) { fm[jj] = s_fmap[jj]; zm[jj] = s_zmap[jj]; }
            const int entry = (warp == 0) ? 0 : find_entry(zm, 56 * warp);
            const int end   = (warp == 3) ? HH : find_entry(zm, 56 * (warp + 1));

            u64 p1 = 0ull, p2 = 0ull;
            if (warp == 0) p1 = (j < 3) ? ~0ull : W3MASK;   // virtual row -1 = ones
            u64 cm = 0ull;
            int hmin = 1 << 30, hmax = -1;
            int e1 = 0, e2 = 0, p1z = 0, nzflag = 0, r0 = entry;
            int r = entry;
            while (r < end) {
                const int w = r >> 5, bpos = r & 31;
                if ((e1 & e2) && ((fm[w] >> bpos) & 1)) {
                    // hit RUN: consecutive rows with b(q)==b(q-1); nn stays == p1
                    int erun;
                    u32 xbits = (~fm[w]) >> bpos;
                    if (xbits) erun = r + __ffs(xbits) - 1;
                    else {
                        int ww = w + 1;
                        while (ww < 7 && fm[ww] == FULLM) ww++;
                        erun = (ww < 7) ? ww * 32 + __ffs(~fm[ww]) - 1 : HH;
                    }
                    if (erun > end) erun = end;
                    for (int q = r + lane; q < erun; q += 32) s_src[q] = r0;
                    if (nzflag) hmax = erun - 1;   // hmin/cm already reflect this value
                    r = erun;
                    continue;
                }
                if ((zm[w] >> bpos) & 1) {
                    // zero RUN: b1|b2==0 -> nn=0 for ANY ab (O=0 keeps seed empty).
                    // Exit state closed-form from unrolling the one-row z-update:
                    //   L==1: e1=p1z0, e2=e1_0, p2=p1_0
                    //   L==2: e1=1,    e2=p1z0, p2=0
                    //   L>=3: e1=1,    e2=1,    p2=0
                    // always: p1=0, p1z=1, nzflag=0.
                    int erun;
                    u32 xbits = (~zm[w]) >> bpos;
                    if (xbits) erun = r + __ffs(xbits) - 1;
                    else {
                        int ww = w + 1;
                        while (ww < 7 && zm[ww] == FULLM) ww++;
                        erun = (ww < 7) ? ww * 32 + __ffs(~zm[ww]) - 1 : HH;
                    }
                    if (erun > end) erun = end;
                    const int L = erun - r;
                    if (lane < 4) s_n[r][j] = 0ull;   // representative zero row
                    for (int q = r + lane; q < erun; q += 32) s_src[q] = r;
                    r0 = r;
                    if (L == 1)      { e2 = e1;  e1 = p1z; p2 = p1; }
                    else if (L == 2) { e2 = p1z; e1 = 1;   p2 = 0ull; }
                    else             { e2 = 1;   e1 = 1;   p2 = 0ull; }
                    p1 = 0ull; p1z = 1; nzflag = 0;
                    r = erun;
                    continue;
                }
                // ---- miss: full row, one 64-bit word per lane ----
                u64 ab = p1 & p2;
                u64 b1 = s_b1[r][j], b2 = s_b2[r][j];
                u64 O = b2 | (b1 & ab);      // a>=2
                u64 P = (b1 ^ ab) & ~b2;     // a==1
                u64 F = 0ull;
                // cross-word bits from lane j-1: [2]=P63, [1]=O63, [0]=O62
                u32 hi = ((u32)(P >> 63) << 2) | ((u32)(O >> 62) & 3u);
                u32 hp = __shfl_up_sync(FULLM, hi, 1);
                u32 sIn = (j == 0) ? 0u : ((hp >> 2) & 1u);
                u32 aIn = (j == 0) ? 1u : ((hp >> 1) & 1u);   // virtual n(-1)=1
                u32 cIn = (j == 0) ? 2u : (hp & 3u);          // virtual n(-2)=0
                u64 S  = P & ~((P << 1) | (u64)sIn);          // run starts
                u64 gs = S & ((O << 1) | (u64)aIn) & ((O << 2) | (u64)cIn);
                // no seed-guard ballot: loop self-terminates in 1 iter when gs==0
                // (gs monotone; F pure function of gs -> iterate on gs)
                for (int it = 0; it < 256; it++) {
                    // 224-bit add P+gs; generate/propagate share one ballot
                    u64 s = P + gs;
                    u32 bal2 = __ballot_sync(FULLM,
                                   loTest ? (s < P) : (s == ~0ull));
                    u32 gm4 = bal2 & 0xFu;           // generate, words 0..3
                    u32 pm4 = (bal2 >> 16) & 0xFu;   // propagate, words 0..3
                    u32 c1 = gm4 & 1u;
                    u32 c2 = ((gm4 >> 1) & 1u) | (((pm4 >> 1) & 1u) & c1);
                    u32 c3 = ((gm4 >> 2) & 1u) | (((pm4 >> 2) & 1u) & c2);
                    u32 cw = (c1 << 1) | (c2 << 2) | (c3 << 3);
                    u64 s2 = s + (u64)((cw >> j) & 1u);
                    F = P & ~s2;                 // filled runs
                    u64 k = O | F;
                    u32 kh  = (u32)(k >> 62) & 3u;   // [1]=k63 [0]=k62
                    u32 khp = __shfl_up_sync(FULLM, kh, 1);
                    u32 aI = (j == 0) ? 1u : ((khp >> 1) & 1u);
                    u32 cI = (j == 0) ? 2u : (khp & 3u);
                    u64 gn = S & ((k << 1) | (u64)aI) & ((k << 2) | (u64)cI);
                    u32 chb = __ballot_sync(FULLM, gn != gs);
                    gs = gn;
                    if (!chb) break;
                }
                u64 nn = O | F;
                if (lane < 4) s_n[r][j] = nn;
                if (lane == 0) s_src[r] = r;
                r0 = r;
                // merged ballot: nibble0 = nn!=p1 per word, nibble4 = nn!=0 per word
                u32 bal = __ballot_sync(FULLM,
                              loTest ? ((nn ^ p1) != 0ull) : (nn != 0ull));
                e2 = e1; e1 = ((bal & 0xFu) == 0u);
                int nz = (((bal >> 16) & 0xFu) != 0u);
                p1z = !nz;
                if (nz) {
                    if (hmax < 0) hmin = r;
                    hmax = r;
                    cm |= nn;
                    nzflag = 1;
                } else {
                    nzflag = 0;
                }
                p2 = p1; p1 = nn;
                r++;
            }
            // per-warp bbox handoff (no atomics; fixed slots)
            if (lane < 4) s_wcm[warp][j] = cm;
            if (lane == 0) { s_whmin[warp] = hmin; s_whmax[warp] = hmax; }
        }
        __syncthreads();   // B1: s_n + per-warp bbox ready

        // ---- fused parallel phase: combine bbox + rect + diff + next b/flags ----
        {
            // every thread combines the 4 warp results (replicated, branch-free)
            int hmin = min(min(s_whmin[0], s_whmin[1]), min(s_whmin[2], s_whmin[3]));
            int hmax = max(max(s_whmax[0], s_whmax[1]), max(s_whmax[2], s_whmax[3]));
            u64 cm0 = s_wcm[0][0] | s_wcm[1][0] | s_wcm[2][0] | s_wcm[3][0];
            u64 cm1 = s_wcm[0][1] | s_wcm[1][1] | s_wcm[2][1] | s_wcm[3][1];
            u64 cm2 = s_wcm[0][2] | s_wcm[1][2] | s_wcm[2][2] | s_wcm[3][2];
            u64 cm3 = s_wcm[0][3] | s_wcm[1][3] | s_wcm[2][3] | s_wcm[3][3];
            int wmin, wmax;
            if (hmax < 0) {   // empty: argmax-of-all-False semantics
                hmin = 0; hmax = HH - 1; wmin = 0; wmax = WW - 1;
            } else {
                if (cm0)      wmin = __ffsll((long long)cm0) - 1;
                else if (cm1) wmin = 64  + __ffsll((long long)cm1) - 1;
                else if (cm2) wmin = 128 + __ffsll((long long)cm2) - 1;
                else          wmin = 192 + __ffsll((long long)cm3) - 1;
                if (cm3)      wmax = 255 - __clzll((long long)cm3);
                else if (cm2) wmax = 191 - __clzll((long long)cm2);
                else if (cm1) wmax = 127 - __clzll((long long)cm1);
                else          wmax = 63  - __clzll((long long)cm0);
            }
            // rect columns [wmin, wmax)  (wmax EXCLUSIVE, matching reference slice)
            const u64 rc0 = mask_lt(wmax, 0) & ~mask_lt(wmin, 0);
            const u64 rc1 = mask_lt(wmax, 1) & ~mask_lt(wmin, 1);
            const u64 rc2 = mask_lt(wmax, 2) & ~mask_lt(wmin, 2);
            const u64 rc3 = mask_lt(wmax, 3) & ~mask_lt(wmin, 3);
            u64 diff = 0;

#define PHASEB_ROW(RR, FLOUT) do {                                             \
        const int r_ = (RR);                                                   \
        const int sr_ = s_src[r_];                                             \
        bool in_ = (r_ >= hmin) && (r_ <= hmax);                               \
        u64 g0 = s_n[sr_][0] | (in_ ? rc0 : 0ull);                             \
        u64 g1 = s_n[sr_][1] | (in_ ? rc1 : 0ull);                             \
        u64 g2 = s_n[sr_][2] | (in_ ? rc2 : 0ull);                             \
        u64 g3 = s_n[sr_][3] | (in_ ? rc3 : 0ull);                             \
        diff |= (g0 ^ s_mask[r_][0]) | (g1 ^ s_mask[r_][1])                    \
              | (g2 ^ s_mask[r_][2]) | (g3 ^ s_mask[r_][3]);                   \
        s_mask[r_][0] = g0; s_mask[r_][1] = g1;                                \
        s_mask[r_][2] = g2; s_mask[r_][3] = g3;                                \
        u64 n0, n1, n2, n3;                                                    \
        if (r_ < HH - 2) {                                                     \
            const int sn_ = s_src[r_ + 1];                                     \
            bool in1_ = (r_ + 1 >= hmin) && (r_ + 1 <= hmax);                  \
            n0 = s_n[sn_][0] | (in1_ ? rc0 : 0ull);                            \
            n1 = s_n[sn_][1] | (in1_ ? rc1 : 0ull);                            \
            n2 = s_n[sn_][2] | (in1_ ? rc2 : 0ull);                            \
            n3 = s_n[sn_][3] | (in1_ ? rc3 : 0ull);                            \
        } else if (r_ == HH - 2) {                                             \
            n0 = ~0ull; n1 = ~0ull; n2 = ~0ull; n3 = W3MASK;                   \
        } else { n0 = n1 = n2 = n3 = 0ull; }                                   \
        u64 bl0 = g0 & n0, bl1 = g1 & n1, bl2 = g2 & n2, bl3 = g3 & n3;        \
        u64 rt0 = ((g0 >> 1) | (g1 << 63)) & g0;                               \
        u64 rt1 = ((g1 >> 1) | (g2 << 63)) & g1;                               \
        u64 rt2 = ((g2 >> 1) | (g3 << 63)) & g2;                               \
        u64 rt3 = ((g3 >> 1) | (1ull << 30)) & g3;                             \
        s_b1[r_][0] = bl0 ^ rt0; s_b1[r_][1] = bl1 ^ rt1;                      \
        s_b1[r_][2] = bl2 ^ rt2; s_b1[r_][3] = bl3 ^ rt3;                      \
        s_b2[r_][0] = bl0 & rt0; s_b2[r_][1] = bl1 & rt1;                      \
        s_b2[r_][2] = bl2 & rt2; s_b2[r_][3] = bl3 & rt3;                      \
        int fl_ = (((bl0 | rt0) | (bl1 | rt1) | (bl2 | rt2) | (bl3 | rt3))     \
                   == 0ull) ? 2 : 0;                                           \
        if (r_ >= 1 && r_ <= HH - 3) {                                         \
            const int sm_ = s_src[r_ - 1];                                     \
            bool inm_ = (r_ - 1 >= hmin) && (r_ - 1 <= hmax);                  \
            u64 m0 = s_n[sm_][0] | (inm_ ? rc0 : 0ull);                        \
            u64 m1 = s_n[sm_][1] | (inm_ ? rc1 : 0ull);                        \
            u64 m2 = s_n[sm_][2] | (inm_ ? rc2 : 0ull);                        \
            u64 m3 = s_n[sm_][3] | (inm_ ? rc3 : 0ull);                        \
            u64 d = (m0 ^ g0) | (m1 ^ g1) | (m2 ^ g2) | (m3 ^ g3)              \
                  | (g0 ^ n0) | (g1 ^ n1) | (g2 ^ n2) | (g3 ^ n3);             \
            fl_ |= (d == 0ull) ? 1 : 0;                                        \
        }                                                                      \
        FLOUT = fl_;                                                           \
    } while (0)

            {
                int fl;
                PHASEB_ROW(tid, fl);
                u32 f1 = __ballot_sync(FULLM, fl & 1);
                u32 f2 = __ballot_sync(FULLM, fl & 2);
                if (lane == 0) { s_fmap[warp] = f1; s_zmap[warp] = f2; }
            }
            if (tid < 96) {
                int fl;
                PHASEB_ROW(128 + tid, fl);
                u32 f1 = __ballot_sync(FULLM, fl & 1);
                u32 f2 = __ballot_sync(FULLM, fl & 2);
                if (lane == 0) { s_fmap[4 + warp] = f1; s_zmap[4 + warp] = f2; }
            }
            if (diff) s_chg[pass] = 1;   // benign multi-writer race (all write 1)
#undef PHASEB_ROW
        }
        __syncthreads();

        // converged: pass(m)==m, all remaining passes are identity
        if (!s_chg[pass]) break;   // write-once flag: no reset, no race
    }

    // ---- unpack to float: one float4 per 4 columns ----
#pragma unroll 4
    for (int idx = tid; idx < IMG / 4; idx += 128) {
        int r = idx / 56, cg = idx - r * 56;
        int col = cg * 4;                       // 4-aligned: nibble within one word
        u32 bits = (u32)(s_mask[r][col >> 6] >> (col & 63)) & 0xFu;
        float4 o;
        o.x = (bits & 1u) ? 1.0f : 0.0f;
        o.y = (bits & 2u) ? 1.0f : 0.0f;
        o.z = (bits & 4u) ? 1.0f : 0.0f;
        o.w = (bits & 8u) ? 1.0f : 0.0f;
        ((float4*)oi)[idx] = o;
    }
}

extern "C" void kernel_launch(void* const* d_in, const int* in_sizes, int n_in,
                              void* d_out, int out_size) {
    const float* x = (const float*)d_in[0];
    float* out = (float*)d_out;
    int nimg = in_sizes[0] / IMG;   // B*C = 8
    mask_ca_kernel<<<nimg, 128>>>(x, out);
}

// round 15
// speedup vs baseline: 1.0971x; 1.0971x over previous
#include <cuda_runtime.h>

typedef unsigned long long u64;
typedef unsigned int u32;

#define HH 224
#define WW 224
#define IMG (HH * WW)
#define NPASS 9
#define W3MASK 0xFFFFFFFFull
#define FULLM 0xFFFFFFFFu

// bits 0..k-1 of word j (j*64 .. j*64+63) of a 224-bit mask
__device__ __forceinline__ u64 mask_lt(int k, int j) {
    int lo = j * 64;
    if (k <= lo) return 0ull;
    if (k >= lo + 64) return ~0ull;
    return (1ull << (k - lo)) - 1ull;
}

// first row e >= q such that row e-1 is a zero-b row (z-bit set); HH if none.
// q >= 1. Segment starting at e may be initialized with (p1,p2)=(0,0): exact
// (ab(e) = nn(e-1)&nn(e-2) = 0 since nn(e-1)=0; ab(e+1) = nn(e)&nn(e-1) = 0).
__device__ __forceinline__ int find_entry(const u32* zm, int q) {
    int pos = q - 1;
    int w = pos >> 5;
    u32 bits = zm[w] & (FULLM << (pos & 31));
    while (bits == 0) {
        if (++w >= 7) return HH;
        bits = zm[w];
    }
    int z = (w << 5) + __ffs(bits) - 1;
    return (z + 1 > HH) ? HH : z + 1;
}

__global__ __launch_bounds__(128) void mask_ca_kernel(const float* __restrict__ x,
                                                      float* __restrict__ out) {
    __shared__ u64 s_mask[HH][4];   // current mask (post rect-fill)
    __shared__ u64 s_b1[HH][4];     // base == exactly one of below/right
    __shared__ u64 s_b2[HH][4];     // base == both
    __shared__ u64 s_n[HH][4];      // serial-scan output (pre rect-fill), sparse via s_src
    __shared__ int s_src[HH];       // representative row: value of row r is s_n[s_src[r]]
    __shared__ u32 s_fmap[8];       // bit r: g(r-1)==g(r)==g(r+1) (=> b(r)==b(r-1))
    __shared__ u32 s_zmap[8];       // bit r: (b1|b2)==0 at row r (carry barrier!)
    __shared__ u64 s_wcm[4][4];     // per-warp column-OR of its rows
    __shared__ int s_whmin[4], s_whmax[4];
    __shared__ int s_chg[NPASS];    // write-once per pass (no reset race)

    const int tid  = threadIdx.x;
    const int lane = tid & 31;
    const int warp = tid >> 5;
    const float* xi = x + (size_t)blockIdx.x * IMG;
    float* oi = out + (size_t)blockIdx.x * IMG;

    // ---- pack input: threshold > 0.8, byte-wise, no ballots, deep MLP ----
    {
        unsigned char* sb = (unsigned char*)s_mask;
#pragma unroll 4
        for (int idx = tid; idx < HH * 32; idx += 128) {
            int r = idx >> 5, b = idx & 31;
            unsigned char v = 0;
            if (b < 28) {
                const float4* p = (const float4*)(xi + r * WW + b * 8);
                float4 a = p[0], c = p[1];
                v = (unsigned char)((a.x > 0.8f)
                  | ((a.y > 0.8f) << 1)
                  | ((a.z > 0.8f) << 2)
                  | ((a.w > 0.8f) << 3)
                  | ((c.x > 0.8f) << 4)
                  | ((c.y > 0.8f) << 5)
                  | ((c.z > 0.8f) << 6)
                  | ((c.w > 0.8f) << 7));
            }
            sb[idx] = v;
        }
    }
    if (tid == 0) {
#pragma unroll
        for (int p = 0; p < NPASS; p++) s_chg[p] = 0;
    }
    __syncthreads();

    // ---- initial b1/b2 + flag bitmaps from packed input ----
#define INIT_ROW(RR, FLOUT) do {                                               \
        const int r_ = (RR);                                                   \
        u64 g0 = s_mask[r_][0], g1 = s_mask[r_][1];                            \
        u64 g2 = s_mask[r_][2], g3 = s_mask[r_][3];                            \
        u64 n0, n1, n2, n3;                                                    \
        if (r_ < HH - 2) {                                                     \
            n0 = s_mask[r_ + 1][0]; n1 = s_mask[r_ + 1][1];                    \
            n2 = s_mask[r_ + 1][2]; n3 = s_mask[r_ + 1][3];                    \
        } else if (r_ == HH - 2) {                                             \
            n0 = ~0ull; n1 = ~0ull; n2 = ~0ull; n3 = W3MASK;                   \
        } else { n0 = n1 = n2 = n3 = 0ull; }                                   \
        u64 bl0 = g0 & n0, bl1 = g1 & n1, bl2 = g2 & n2, bl3 = g3 & n3;        \
        u64 rt0 = ((g0 >> 1) | (g1 << 63)) & g0;                               \
        u64 rt1 = ((g1 >> 1) | (g2 << 63)) & g1;                               \
        u64 rt2 = ((g2 >> 1) | (g3 << 63)) & g2;                               \
        u64 rt3 = ((g3 >> 1) | (1ull << 30)) & g3;                             \
        s_b1[r_][0] = bl0 ^ rt0; s_b1[r_][1] = bl1 ^ rt1;                      \
        s_b1[r_][2] = bl2 ^ rt2; s_b1[r_][3] = bl3 ^ rt3;                      \
        s_b2[r_][0] = bl0 & rt0; s_b2[r_][1] = bl1 & rt1;                      \
        s_b2[r_][2] = bl2 & rt2; s_b2[r_][3] = bl3 & rt3;                      \
        int fl_ = (((bl0 | rt0) | (bl1 | rt1) | (bl2 | rt2) | (bl3 | rt3))     \
                   == 0ull) ? 2 : 0;                                           \
        if (r_ >= 1 && r_ <= HH - 3) {                                         \
            u64 m0 = s_mask[r_ - 1][0], m1 = s_mask[r_ - 1][1];                \
            u64 m2 = s_mask[r_ - 1][2], m3 = s_mask[r_ - 1][3];                \
            u64 d = (m0 ^ g0) | (m1 ^ g1) | (m2 ^ g2) | (m3 ^ g3)              \
                  | (g0 ^ n0) | (g1 ^ n1) | (g2 ^ n2) | (g3 ^ n3);             \
            fl_ |= (d == 0ull) ? 1 : 0;                                        \
        }                                                                      \
        FLOUT = fl_;                                                           \
    } while (0)

    {
        int fl;
        INIT_ROW(tid, fl);
        u32 f1 = __ballot_sync(FULLM, fl & 1);
        u32 f2 = __ballot_sync(FULLM, fl & 2);
        if (lane == 0) { s_fmap[warp] = f1; s_zmap[warp] = f2; }
    }
    if (tid < 96) {
        int fl;
        INIT_ROW(128 + tid, fl);
        u32 f1 = __ballot_sync(FULLM, fl & 1);
        u32 f2 = __ballot_sync(FULLM, fl & 2);
        if (lane == 0) { s_fmap[4 + warp] = f1; s_zmap[4 + warp] = f2; }
    }
    __syncthreads();

    for (int pass = 0; pass < NPASS; pass++) {
        // ---- serial raster recurrence, 4 warps on disjoint segments ----
        {
            const int j = lane & 3;
            const bool loTest = (lane < 16);
            u32 fm[7], zm[7];
#pragma unroll
            for (int jj = 0; jj < 7; jj++) { fm[jj] = s_fmap[jj]; zm[jj] = s_zmap[jj]; }
            const int entry = (warp == 0) ? 0 : find_entry(zm, 56 * warp);
            const int end   = (warp == 3) ? HH : find_entry(zm, 56 * (warp + 1));

            u64 p1 = 0ull, p2 = 0ull;
            if (warp == 0) p1 = (j < 3) ? ~0ull : W3MASK;   // virtual row -1 = ones
            u64 cm = 0ull;
            int hmin = 1 << 30, hmax = -1;
            int e1 = 0, e2 = 0, p1z = 0, nzflag = 0, r0 = entry;
            int r = entry;
            while (r < end) {
                const int w = r >> 5, bpos = r & 31;
                if ((e1 & e2) && ((fm[w] >> bpos) & 1)) {
                    // hit RUN: consecutive rows with b(q)==b(q-1); nn stays == p1
                    int erun;
                    u32 xbits = (~fm[w]) >> bpos;
                    if (xbits) erun = r + __ffs(xbits) - 1;
                    else {
                        int ww = w + 1;
                        while (ww < 7 && fm[ww] == FULLM) ww++;
                        erun = (ww < 7) ? ww * 32 + __ffs(~fm[ww]) - 1 : HH;
                    }
                    if (erun > end) erun = end;
                    for (int q = r + lane; q < erun; q += 32) s_src[q] = r0;
                    if (nzflag) hmax = erun - 1;   // hmin/cm already reflect this value
                    r = erun;
                    continue;
                }
                if ((zm[w] >> bpos) & 1) {
                    // zero RUN: b1|b2==0 -> nn=0 for ANY ab (O=0 keeps seed empty).
                    // Exit state closed-form from unrolling the one-row z-update:
                    //   L==1: e1=p1z0, e2=e1_0, p2=p1_0
                    //   L==2: e1=1,    e2=p1z0, p2=0
                    //   L>=3: e1=1,    e2=1,    p2=0
                    // always: p1=0, p1z=1, nzflag=0.
                    int erun;
                    u32 xbits = (~zm[w]) >> bpos;
                    if (xbits) erun = r + __ffs(xbits) - 1;
                    else {
                        int ww = w + 1;
                        while (ww < 7 && zm[ww] == FULLM) ww++;
                        erun = (ww < 7) ? ww * 32 + __ffs(~zm[ww]) - 1 : HH;
                    }
                    if (erun > end) erun = end;
                    const int L = erun - r;
                    if (lane < 4) s_n[r][j] = 0ull;   // representative zero row
                    for (int q = r + lane; q < erun; q += 32) s_src[q] = r;
                    r0 = r;
                    if (L == 1)      { e2 = e1;  e1 = p1z; p2 = p1; }
                    else if (L == 2) { e2 = p1z; e1 = 1;   p2 = 0ull; }
                    else             { e2 = 1;   e1 = 1;   p2 = 0ull; }
                    p1 = 0ull; p1z = 1; nzflag = 0;
                    r = erun;
                    continue;
                }
                // ---- miss: full row, one 64-bit word per lane ----
                u64 ab = p1 & p2;
                u64 b1 = s_b1[r][j], b2 = s_b2[r][j];
                u64 O = b2 | (b1 & ab);      // a>=2
                u64 P = (b1 ^ ab) & ~b2;     // a==1
                u64 F = 0ull;
                // cross-word bits from lane j-1: [2]=P63, [1]=O63, [0]=O62
                u32 hi = ((u32)(P >> 63) << 2) | ((u32)(O >> 62) & 3u);
                u32 hp = __shfl_up_sync(FULLM, hi, 1);
                u32 sIn = (j == 0) ? 0u : ((hp >> 2) & 1u);
                u32 aIn = (j == 0) ? 1u : ((hp >> 1) & 1u);   // virtual n(-1)=1
                u32 cIn = (j == 0) ? 2u : (hp & 3u);          // virtual n(-2)=0
                u64 S  = P & ~((P << 1) | (u64)sIn);          // run starts
                u64 gs = S & ((O << 1) | (u64)aIn) & ((O << 2) | (u64)cIn);
                // seed-guard ballot: fill loop is rare — skip it when no run seeded
                u32 gb = __ballot_sync(FULLM, gs != 0ull);
                if (gb) {
                    // gs monotone; F pure function of gs -> iterate on gs
                    for (int it = 0; it < 256; it++) {
                        // 224-bit add P+gs; generate/propagate share one ballot
                        u64 s = P + gs;
                        u32 bal2 = __ballot_sync(FULLM,
                                       loTest ? (s < P) : (s == ~0ull));
                        u32 gm4 = bal2 & 0xFu;           // generate, words 0..3
                        u32 pm4 = (bal2 >> 16) & 0xFu;   // propagate, words 0..3
                        u32 c1 = gm4 & 1u;
                        u32 c2 = ((gm4 >> 1) & 1u) | (((pm4 >> 1) & 1u) & c1);
                        u32 c3 = ((gm4 >> 2) & 1u) | (((pm4 >> 2) & 1u) & c2);
                        u32 cw = (c1 << 1) | (c2 << 2) | (c3 << 3);
                        u64 s2 = s + (u64)((cw >> j) & 1u);
                        F = P & ~s2;                 // filled runs
                        u64 k = O | F;
                        u32 kh  = (u32)(k >> 62) & 3u;   // [1]=k63 [0]=k62
                        u32 khp = __shfl_up_sync(FULLM, kh, 1);
                        u32 aI = (j == 0) ? 1u : ((khp >> 1) & 1u);
                        u32 cI = (j == 0) ? 2u : (khp & 3u);
                        u64 gn = S & ((k << 1) | (u64)aI) & ((k << 2) | (u64)cI);
                        u32 chb = __ballot_sync(FULLM, gn != gs);
                        gs = gn;
                        if (!chb) break;
                    }
                }
                u64 nn = O | F;
                if (lane < 4) s_n[r][j] = nn;
                if (lane == 0) s_src[r] = r;
                r0 = r;
                // merged ballot: nibble0 = nn!=p1 per word, nibble4 = nn!=0 per word
                u32 bal = __ballot_sync(FULLM,
                              loTest ? ((nn ^ p1) != 0ull) : (nn != 0ull));
                e2 = e1; e1 = ((bal & 0xFu) == 0u);
                int nz = (((bal >> 16) & 0xFu) != 0u);
                p1z = !nz;
                if (nz) {
                    if (hmax < 0) hmin = r;
                    hmax = r;
                    cm |= nn;
                    nzflag = 1;
                } else {
                    nzflag = 0;
                }
                p2 = p1; p1 = nn;
                r++;
            }
            // per-warp bbox handoff (no atomics; fixed slots)
            if (lane < 4) s_wcm[warp][j] = cm;
            if (lane == 0) { s_whmin[warp] = hmin; s_whmax[warp] = hmax; }
        }
        __syncthreads();   // B1: s_n + per-warp bbox ready

        // ---- fused parallel phase: combine bbox + rect + diff + next b/flags ----
        {
            // every thread combines the 4 warp results (replicated, branch-free)
            int hmin = min(min(s_whmin[0], s_whmin[1]), min(s_whmin[2], s_whmin[3]));
            int hmax = max(max(s_whmax[0], s_whmax[1]), max(s_whmax[2], s_whmax[3]));
            u64 cm0 = s_wcm[0][0] | s_wcm[1][0] | s_wcm[2][0] | s_wcm[3][0];
            u64 cm1 = s_wcm[0][1] | s_wcm[1][1] | s_wcm[2][1] | s_wcm[3][1];
            u64 cm2 = s_wcm[0][2] | s_wcm[1][2] | s_wcm[2][2] | s_wcm[3][2];
            u64 cm3 = s_wcm[0][3] | s_wcm[1][3] | s_wcm[2][3] | s_wcm[3][3];
            int wmin, wmax;
            if (hmax < 0) {   // empty: argmax-of-all-False semantics
                hmin = 0; hmax = HH - 1; wmin = 0; wmax = WW - 1;
            } else {
                if (cm0)      wmin = __ffsll((long long)cm0) - 1;
                else if (cm1) wmin = 64  + __ffsll((long long)cm1) - 1;
                else if (cm2) wmin = 128 + __ffsll((long long)cm2) - 1;
                else          wmin = 192 + __ffsll((long long)cm3) - 1;
                if (cm3)      wmax = 255 - __clzll((long long)cm3);
                else if (cm2) wmax = 191 - __clzll((long long)cm2);
                else if (cm1) wmax = 127 - __clzll((long long)cm1);
                else          wmax = 63  - __clzll((long long)cm0);
            }
            // rect columns [wmin, wmax)  (wmax EXCLUSIVE, matching reference slice)
            const u64 rc0 = mask_lt(wmax, 0) & ~mask_lt(wmin, 0);
            const u64 rc1 = mask_lt(wmax, 1) & ~mask_lt(wmin, 1);
            const u64 rc2 = mask_lt(wmax, 2) & ~mask_lt(wmin, 2);
            const u64 rc3 = mask_lt(wmax, 3) & ~mask_lt(wmin, 3);
            u64 diff = 0;

#define PHASEB_ROW(RR, FLOUT) do {                                             \
        const int r_ = (RR);                                                   \
        const int sr_ = s_src[r_];                                             \
        bool in_ = (r_ >= hmin) && (r_ <= hmax);                               \
        u64 g0 = s_n[sr_][0] | (in_ ? rc0 : 0ull);                             \
        u64 g1 = s_n[sr_][1] | (in_ ? rc1 : 0ull);                             \
        u64 g2 = s_n[sr_][2] | (in_ ? rc2 : 0ull);                             \
        u64 g3 = s_n[sr_][3] | (in_ ? rc3 : 0ull);                             \
        diff |= (g0 ^ s_mask[r_][0]) | (g1 ^ s_mask[r_][1])                    \
              | (g2 ^ s_mask[r_][2]) | (g3 ^ s_mask[r_][3]);                   \
        s_mask[r_][0] = g0; s_mask[r_][1] = g1;                                \
        s_mask[r_][2] = g2; s_mask[r_][3] = g3;                                \
        u64 n0, n1, n2, n3;                                                    \
        if (r_ < HH - 2) {                                                     \
            const int sn_ = s_src[r_ + 1];                                     \
            bool in1_ = (r_ + 1 >= hmin) && (r_ + 1 <= hmax);                  \
            n0 = s_n[sn_][0] | (in1_ ? rc0 : 0ull);                            \
            n1 = s_n[sn_][1] | (in1_ ? rc1 : 0ull);                            \
            n2 = s_n[sn_][2] | (in1_ ? rc2 : 0ull);                            \
            n3 = s_n[sn_][3] | (in1_ ? rc3 : 0ull);                            \
        } else if (r_ == HH - 2) {                                             \
            n0 = ~0ull; n1 = ~0ull; n2 = ~0ull; n3 = W3MASK;                   \
        } else { n0 = n1 = n2 = n3 = 0ull; }                                   \
        u64 bl0 = g0 & n0, bl1 = g1 & n1, bl2 = g2 & n2, bl3 = g3 & n3;        \
        u64 rt0 = ((g0 >> 1) | (g1 << 63)) & g0;                               \
        u64 rt1 = ((g1 >> 1) | (g2 << 63)) & g1;                               \
        u64 rt2 = ((g2 >> 1) | (g3 << 63)) & g2;                               \
        u64 rt3 = ((g3 >> 1) | (1ull << 30)) & g3;                             \
        s_b1[r_][0] = bl0 ^ rt0; s_b1[r_][1] = bl1 ^ rt1;                      \
        s_b1[r_][2] = bl2 ^ rt2; s_b1[r_][3] = bl3 ^ rt3;                      \
        s_b2[r_][0] = bl0 & rt0; s_b2[r_][1] = bl1 & rt1;                      \
        s_b2[r_][2] = bl2 & rt2; s_b2[r_][3] = bl3 & rt3;                      \
        int fl_ = (((bl0 | rt0) | (bl1 | rt1) | (bl2 | rt2) | (bl3 | rt3))     \
                   == 0ull) ? 2 : 0;                                           \
        if (r_ >= 1 && r_ <= HH - 3) {                                         \
            const int sm_ = s_src[r_ - 1];                                     \
            bool inm_ = (r_ - 1 >= hmin) && (r_ - 1 <= hmax);                  \
            u64 m0 = s_n[sm_][0] | (inm_ ? rc0 : 0ull);                        \
            u64 m1 = s_n[sm_][1] | (inm_ ? rc1 : 0ull);                        \
            u64 m2 = s_n[sm_][2] | (inm_ ? rc2 : 0ull);                        \
            u64 m3 = s_n[sm_][3] | (inm_ ? rc3 : 0ull);                        \
            u64 d = (m0 ^ g0) | (m1 ^ g1) | (m2 ^ g2) | (m3 ^ g3)              \
                  | (g0 ^ n0) | (g1 ^ n1) | (g2 ^ n2) | (g3 ^ n3);             \
            fl_ |= (d == 0ull) ? 1 : 0;                                        \
        }                                                                      \
        FLOUT = fl_;                                                           \
    } while (0)

            {
                int fl;
                PHASEB_ROW(tid, fl);
                u32 f1 = __ballot_sync(FULLM, fl & 1);
                u32 f2 = __ballot_sync(FULLM, fl & 2);
                if (lane == 0) { s_fmap[warp] = f1; s_zmap[warp] = f2; }
            }
            if (tid < 96) {
                int fl;
                PHASEB_ROW(128 + tid, fl);
                u32 f1 = __ballot_sync(FULLM, fl & 1);
                u32 f2 = __ballot_sync(FULLM, fl & 2);
                if (lane == 0) { s_fmap[4 + warp] = f1; s_zmap[4 + warp] = f2; }
            }
            if (diff) s_chg[pass] = 1;   // benign multi-writer race (all write 1)
#undef PHASEB_ROW
        }
        __syncthreads();

        // converged: pass(m)==m, all remaining passes are identity
        if (!s_chg[pass]) break;   // write-once flag: no reset, no race
    }

    // ---- unpack to float: one float4 per 4 columns ----
#pragma unroll 4
    for (int idx = tid; idx < IMG / 4; idx += 128) {
        int r = idx / 56, cg = idx - r * 56;
        int col = cg * 4;                       // 4-aligned: nibble within one word
        u32 bits = (u32)(s_mask[r][col >> 6] >> (col & 63)) & 0xFu;
        float4 o;
        o.x = (bits & 1u) ? 1.0f : 0.0f;
        o.y = (bits & 2u) ? 1.0f : 0.0f;
        o.z = (bits & 4u) ? 1.0f : 0.0f;
        o.w = (bits & 8u) ? 1.0f : 0.0f;
        ((float4*)oi)[idx] = o;
    }
}

extern "C" void kernel_launch(void* const* d_in, const int* in_sizes, int n_in,
                              void* d_out, int out_size) {
    const float* x = (const float*)d_in[0];
    float* out = (float*)d_out;
    int nimg = in_sizes[0] / IMG;   // B*C = 8
    mask_ca_kernel<<<nimg, 128>>>(x, out);
}

// round 16
// speedup vs baseline: 1.1280x; 1.0282x over previous
#include <cuda_runtime.h>

typedef unsigned long long u64;
typedef unsigned int u32;

#define HH 224
#define WW 224
#define IMG (HH * WW)
#define NPASS 9
#define W3MASK 0xFFFFFFFFull
#define FULLM 0xFFFFFFFFu

// bits 0..k-1 of word j (j*64 .. j*64+63) of a 224-bit mask
__device__ __forceinline__ u64 mask_lt(int k, int j) {
    int lo = j * 64;
    if (k <= lo) return 0ull;
    if (k >= lo + 64) return ~0ull;
    return (1ull << (k - lo)) - 1ull;
}

// first row e >= q such that row e-1 is a zero-b row (z-bit set); HH if none.
// q >= 1. Segment starting at e may be initialized with (p1,p2)=(0,0): exact
// (nn(e-1)=0 forces ab(e)=0 and ab(e+1)=0).
__device__ __forceinline__ int find_entry(const u32* zm, int q) {
    int pos = q - 1;
    int w = pos >> 5;
    u32 bits = zm[w] & (FULLM << (pos & 31));
    while (bits == 0) {
        if (++w >= 7) return HH;
        bits = zm[w];
    }
    int z = (w << 5) + __ffs(bits) - 1;
    return (z + 1 > HH) ? HH : z + 1;
}

__global__ __launch_bounds__(128) void mask_ca_kernel(const float* __restrict__ x,
                                                      float* __restrict__ out) {
    __shared__ u64 s_mask[HH][4];   // current mask (post rect-fill)
    __shared__ u64 s_b1[HH][4];     // base == exactly one of below/right
    __shared__ u64 s_b2[HH][4];     // base == both
    __shared__ u64 s_n[HH][4];      // serial-scan output (pre rect-fill), sparse via s_src
    __shared__ int s_src[HH];       // representative row: value of row r is s_n[s_src[r]]
    __shared__ u32 s_fmap[8];       // bit r: g(r-1)==g(r)==g(r+1) (=> b(r)==b(r-1))
    __shared__ u32 s_zmap[8];       // bit r: (b1|b2)==0 at row r (carry barrier!)
    __shared__ u64 s_wcm[4][4];     // per-warp column-OR of its rows
    __shared__ int s_whmin[4], s_whmax[4];
    __shared__ int s_chg[NPASS];    // write-once per pass (no reset race)

    const int tid  = threadIdx.x;
    const int lane = tid & 31;
    const int warp = tid >> 5;
    const float* xi = x + (size_t)blockIdx.x * IMG;
    float* oi = out + (size_t)blockIdx.x * IMG;

    // ---- pack input: threshold > 0.8, byte-wise, no ballots, deep MLP ----
    {
        unsigned char* sb = (unsigned char*)s_mask;
#pragma unroll 4
        for (int idx = tid; idx < HH * 32; idx += 128) {
            int r = idx >> 5, b = idx & 31;
            unsigned char v = 0;
            if (b < 28) {
                const float4* p = (const float4*)(xi + r * WW + b * 8);
                float4 a = p[0], c = p[1];
                v = (unsigned char)((a.x > 0.8f)
                  | ((a.y > 0.8f) << 1)
                  | ((a.z > 0.8f) << 2)
                  | ((a.w > 0.8f) << 3)
                  | ((c.x > 0.8f) << 4)
                  | ((c.y > 0.8f) << 5)
                  | ((c.z > 0.8f) << 6)
                  | ((c.w > 0.8f) << 7));
            }
            sb[idx] = v;
        }
    }
    if (tid == 0) {
#pragma unroll
        for (int p = 0; p < NPASS; p++) s_chg[p] = 0;
    }
    __syncthreads();

    // ---- initial b1/b2 + flag bitmaps from packed input ----
#define INIT_ROW(RR, FLOUT) do {                                               \
        const int r_ = (RR);                                                   \
        u64 g0 = s_mask[r_][0], g1 = s_mask[r_][1];                            \
        u64 g2 = s_mask[r_][2], g3 = s_mask[r_][3];                            \
        u64 n0, n1, n2, n3;                                                    \
        if (r_ < HH - 2) {                                                     \
            n0 = s_mask[r_ + 1][0]; n1 = s_mask[r_ + 1][1];                    \
            n2 = s_mask[r_ + 1][2]; n3 = s_mask[r_ + 1][3];                    \
        } else if (r_ == HH - 2) {                                             \
            n0 = ~0ull; n1 = ~0ull; n2 = ~0ull; n3 = W3MASK;                   \
        } else { n0 = n1 = n2 = n3 = 0ull; }                                   \
        u64 bl0 = g0 & n0, bl1 = g1 & n1, bl2 = g2 & n2, bl3 = g3 & n3;        \
        u64 rt0 = ((g0 >> 1) | (g1 << 63)) & g0;                               \
        u64 rt1 = ((g1 >> 1) | (g2 << 63)) & g1;                               \
        u64 rt2 = ((g2 >> 1) | (g3 << 63)) & g2;                               \
        u64 rt3 = ((g3 >> 1) | (1ull << 30)) & g3;                             \
        s_b1[r_][0] = bl0 ^ rt0; s_b1[r_][1] = bl1 ^ rt1;                      \
        s_b1[r_][2] = bl2 ^ rt2; s_b1[r_][3] = bl3 ^ rt3;                      \
        s_b2[r_][0] = bl0 & rt0; s_b2[r_][1] = bl1 & rt1;                      \
        s_b2[r_][2] = bl2 & rt2; s_b2[r_][3] = bl3 & rt3;                      \
        int fl_ = (((bl0 | rt0) | (bl1 | rt1) | (bl2 | rt2) | (bl3 | rt3))     \
                   == 0ull) ? 2 : 0;                                           \
        if (r_ >= 1 && r_ <= HH - 3) {                                         \
            u64 m0 = s_mask[r_ - 1][0], m1 = s_mask[r_ - 1][1];                \
            u64 m2 = s_mask[r_ - 1][2], m3 = s_mask[r_ - 1][3];                \
            u64 d = (m0 ^ g0) | (m1 ^ g1) | (m2 ^ g2) | (m3 ^ g3)              \
                  | (g0 ^ n0) | (g1 ^ n1) | (g2 ^ n2) | (g3 ^ n3);             \
            fl_ |= (d == 0ull) ? 1 : 0;                                        \
        }                                                                      \
        FLOUT = fl_;                                                           \
    } while (0)

    {
        int fl;
        INIT_ROW(tid, fl);
        u32 f1 = __ballot_sync(FULLM, fl & 1);
        u32 f2 = __ballot_sync(FULLM, fl & 2);
        if (lane == 0) { s_fmap[warp] = f1; s_zmap[warp] = f2; }
    }
    if (tid < 96) {
        int fl;
        INIT_ROW(128 + tid, fl);
        u32 f1 = __ballot_sync(FULLM, fl & 1);
        u32 f2 = __ballot_sync(FULLM, fl & 2);
        if (lane == 0) { s_fmap[4 + warp] = f1; s_zmap[4 + warp] = f2; }
    }
    __syncthreads();

    for (int pass = 0; pass < NPASS; pass++) {
        // ---- serial raster recurrence, 4 warps on disjoint segments ----
        {
            const int j = lane & 3;
            const int jm = j ? (j - 1) : 0;   // word j-1 (dummy for j==0)
            const bool loTest = (lane < 16);
            const u32 grp = lane >> 2;
            const bool isChb = (grp < 2);          // lanes 0-7:  gn != gs
            const bool isE1  = (grp >= 2 && grp < 4); // lanes 8-15: nn != p1
            u32 fm[7], zm[7];
#pragma unroll
            for (int jj = 0; jj < 7; jj++) { fm[jj] = s_fmap[jj]; zm[jj] = s_zmap[jj]; }
            const int entry = (warp == 0) ? 0 : find_entry(zm, 56 * warp);
            const int end   = (warp == 3) ? HH : find_entry(zm, 56 * (warp + 1));

            u64 p1 = 0ull, p2 = 0ull;
            u64 pm1 = 0ull, pm2 = 0ull;   // history of word j-1 (exact mirror)
            if (warp == 0) {
                p1 = (j < 3) ? ~0ull : W3MASK;   // virtual row -1 = ones
                pm1 = (j > 0) ? ~0ull : 0ull;     // word j-1 of row -1 (j==0 unused)
            }
            u64 cm = 0ull;
            int hmin = 1 << 30, hmax = -1;
            int e1 = 0, e2 = 0, p1z = 0, nzflag = 0, r0 = entry;
            int r = entry;
            while (r < end) {
                const int w = r >> 5, bpos = r & 31;
                if ((e1 & e2) && ((fm[w] >> bpos) & 1)) {
                    // hit RUN: consecutive rows with b(q)==b(q-1); nn stays == p1
                    int erun;
                    u32 xbits = (~fm[w]) >> bpos;
                    if (xbits) erun = r + __ffs(xbits) - 1;
                    else {
                        int ww = w + 1;
                        while (ww < 7 && fm[ww] == FULLM) ww++;
                        erun = (ww < 7) ? ww * 32 + __ffs(~fm[ww]) - 1 : HH;
                    }
                    if (erun > end) erun = end;
                    for (int q = r + lane; q < erun; q += 32) s_src[q] = r0;
                    if (nzflag) hmax = erun - 1;   // state unchanged across the run
                    r = erun;
                    continue;
                }
                if ((zm[w] >> bpos) & 1) {
                    // zero row: b1|b2==0 -> nn=0 for ANY ab (O=0 keeps seed empty)
                    if (lane < 4) s_n[r][j] = 0ull;
                    if (lane == 0) s_src[r] = r;
                    r0 = r;
                    e2 = e1; e1 = p1z; p1z = 1; nzflag = 0;
                    p2 = p1; p1 = 0ull;
                    pm2 = pm1; pm1 = 0ull;   // mirror
                    r++;
                    continue;
                }
                // ---- miss: full row, one 64-bit word per lane ----
                u64 ab  = p1 & p2;
                u64 abm = pm1 & pm2;                    // off-chain (j>0)
                u64 b1 = s_b1[r][j],  b2 = s_b2[r][j];
                u64 b1m = s_b1[r][jm], b2m = s_b2[r][jm]; // latency-parallel LDS
                u64 O = b2 | (b1 & ab);      // a>=2
                u64 P = (b1 ^ ab) & ~b2;     // a==1
                // word j-1 top bits computed LOCALLY (no shfl on the chain)
                u64 Om = b2m | (b1m & abm);
                u64 Pm = (b1m ^ abm) & ~b2m;
                u32 sIn = (j == 0) ? 0u : (u32)(Pm >> 63);
                u32 aIn = (j == 0) ? 1u : ((u32)(Om >> 63) & 1u);  // virtual n(-1)=1
                u32 cIn = (j == 0) ? 2u : ((u32)(Om >> 62) & 3u);  // virtual n(-2)=0
                u64 S  = P & ~((P << 1) | (u64)sIn);               // run starts
                u64 gs = S & ((O << 1) | (u64)aIn) & ((O << 2) | (u64)cIn);
                u64 F = 0ull, nn;
                u32 e1n, nzn;
                u32 gb = __ballot_sync(FULLM, gs != 0ull);
                if (gb) {
                    // gs monotone; F pure function of gs -> iterate on gs.
                    // convergence + e1 + nz share ONE 3-way split ballot.
                    u32 bal3 = 0;
                    for (int it = 0; it < 256; it++) {
                        // 224-bit add P+gs; generate/propagate share one ballot
                        u64 s = P + gs;
                        u32 bal2 = __ballot_sync(FULLM,
                                       loTest ? (s < P) : (s == ~0ull));
                        u32 gm4 = bal2 & 0xFu;           // generate, words 0..3
                        u32 pm4 = (bal2 >> 16) & 0xFu;   // propagate, words 0..3
                        u32 c1 = gm4 & 1u;
                        u32 c2 = ((gm4 >> 1) & 1u) | (((pm4 >> 1) & 1u) & c1);
                        u32 c3 = ((gm4 >> 2) & 1u) | (((pm4 >> 2) & 1u) & c2);
                        u32 cw = (c1 << 1) | (c2 << 2) | (c3 << 3);
                        u64 s2 = s + (u64)((cw >> j) & 1u);
                        F = P & ~s2;                 // filled runs
                        u64 k = O | F;
                        u32 kh  = (u32)(k >> 62) & 3u;   // [1]=k63 [0]=k62
                        u32 khp = __shfl_up_sync(FULLM, kh, 1);
                        u32 aI = (j == 0) ? 1u : ((khp >> 1) & 1u);
                        u32 cI = (j == 0) ? 2u : (khp & 3u);
                        u64 gn = S & ((k << 1) | (u64)aI) & ((k << 2) | (u64)cI);
                        nn = O | F;
                        bal3 = __ballot_sync(FULLM,
                                   isChb ? (gn != gs)
                                         : (isE1 ? ((nn ^ p1) != 0ull)
                                                 : (nn != 0ull)));
                        gs = gn;
                        if (!(bal3 & 0xFFu)) break;   // converged
                    }
                    e1n = (((bal3 >> 8) & 0xFFu) == 0u);
                    nzn = (((bal3 >> 16) & 0xFFFFu) != 0u);
                } else {
                    nn = O;   // F = 0
                    u32 bal = __ballot_sync(FULLM,
                                  loTest ? ((nn ^ p1) != 0ull) : (nn != 0ull));
                    e1n = ((bal & 0xFu) == 0u);
                    nzn = (((bal >> 16) & 0xFu) != 0u);
                }
                if (lane < 4) s_n[r][j] = nn;
                if (lane == 0) s_src[r] = r;
                r0 = r;
                // pm1 via shfl issued here; result not needed until mid-next-row
                u64 pmn = __shfl_up_sync(FULLM, nn, 1);
                e2 = e1; e1 = (int)e1n;
                p1z = !nzn;
                if (nzn) {
                    if (hmax < 0) hmin = r;
                    hmax = r;
                    cm |= nn;
                    nzflag = 1;
                } else {
                    nzflag = 0;
                }
                p2 = p1; p1 = nn;
                pm2 = pm1; pm1 = pmn;
                r++;
            }
            // per-warp bbox handoff (no atomics; fixed slots)
            if (lane < 4) s_wcm[warp][j] = cm;
            if (lane == 0) { s_whmin[warp] = hmin; s_whmax[warp] = hmax; }
        }
        __syncthreads();   // B1: s_n + per-warp bbox ready

        // ---- fused parallel phase: combine bbox + rect + diff + next b/flags ----
        {
            // every thread combines the 4 warp results (replicated, branch-free)
            int hmin = min(min(s_whmin[0], s_whmin[1]), min(s_whmin[2], s_whmin[3]));
            int hmax = max(max(s_whmax[0], s_whmax[1]), max(s_whmax[2], s_whmax[3]));
            u64 cm0 = s_wcm[0][0] | s_wcm[1][0] | s_wcm[2][0] | s_wcm[3][0];
            u64 cm1 = s_wcm[0][1] | s_wcm[1][1] | s_wcm[2][1] | s_wcm[3][1];
            u64 cm2 = s_wcm[0][2] | s_wcm[1][2] | s_wcm[2][2] | s_wcm[3][2];
            u64 cm3 = s_wcm[0][3] | s_wcm[1][3] | s_wcm[2][3] | s_wcm[3][3];
            int wmin, wmax;
            if (hmax < 0) {   // empty: argmax-of-all-False semantics
                hmin = 0; hmax = HH - 1; wmin = 0; wmax = WW - 1;
            } else {
                if (cm0)      wmin = __ffsll((long long)cm0) - 1;
                else if (cm1) wmin = 64  + __ffsll((long long)cm1) - 1;
                else if (cm2) wmin = 128 + __ffsll((long long)cm2) - 1;
                else          wmin = 192 + __ffsll((long long)cm3) - 1;
                if (cm3)      wmax = 255 - __clzll((long long)cm3);
                else if (cm2) wmax = 191 - __clzll((long long)cm2);
                else if (cm1) wmax = 127 - __clzll((long long)cm1);
                else          wmax = 63  - __clzll((long long)cm0);
            }
            // rect columns [wmin, wmax)  (wmax EXCLUSIVE, matching reference slice)
            const u64 rc0 = mask_lt(wmax, 0) & ~mask_lt(wmin, 0);
            const u64 rc1 = mask_lt(wmax, 1) & ~mask_lt(wmin, 1);
            const u64 rc2 = mask_lt(wmax, 2) & ~mask_lt(wmin, 2);
            const u64 rc3 = mask_lt(wmax, 3) & ~mask_lt(wmin, 3);
            u64 diff = 0;

#define PHASEB_ROW(RR, FLOUT) do {                                             \
        const int r_ = (RR);                                                   \
        const int sr_ = s_src[r_];                                             \
        bool in_ = (r_ >= hmin) && (r_ <= hmax);                               \
        u64 g0 = s_n[sr_][0] | (in_ ? rc0 : 0ull);                             \
        u64 g1 = s_n[sr_][1] | (in_ ? rc1 : 0ull);                             \
        u64 g2 = s_n[sr_][2] | (in_ ? rc2 : 0ull);                             \
        u64 g3 = s_n[sr_][3] | (in_ ? rc3 : 0ull);                             \
        diff |= (g0 ^ s_mask[r_][0]) | (g1 ^ s_mask[r_][1])                    \
              | (g2 ^ s_mask[r_][2]) | (g3 ^ s_mask[r_][3]);                   \
        s_mask[r_][0] = g0; s_mask[r_][1] = g1;                                \
        s_mask[r_][2] = g2; s_mask[r_][3] = g3;                                \
        u64 n0, n1, n2, n3;                                                    \
        if (r_ < HH - 2) {                                                     \
            const int sn_ = s_src[r_ + 1];                                     \
            bool in1_ = (r_ + 1 >= hmin) && (r_ + 1 <= hmax);                  \
            n0 = s_n[sn_][0] | (in1_ ? rc0 : 0ull);                            \
            n1 = s_n[sn_][1] | (in1_ ? rc1 : 0ull);                            \
            n2 = s_n[sn_][2] | (in1_ ? rc2 : 0ull);                            \
            n3 = s_n[sn_][3] | (in1_ ? rc3 : 0ull);                            \
        } else if (r_ == HH - 2) {                                             \
            n0 = ~0ull; n1 = ~0ull; n2 = ~0ull; n3 = W3MASK;                   \
        } else { n0 = n1 = n2 = n3 = 0ull; }                                   \
        u64 bl0 = g0 & n0, bl1 = g1 & n1, bl2 = g2 & n2, bl3 = g3 & n3;        \
        u64 rt0 = ((g0 >> 1) | (g1 << 63)) & g0;                               \
        u64 rt1 = ((g1 >> 1) | (g2 << 63)) & g1;                               \
        u64 rt2 = ((g2 >> 1) | (g3 << 63)) & g2;                               \
        u64 rt3 = ((g3 >> 1) | (1ull << 30)) & g3;                             \
        s_b1[r_][0] = bl0 ^ rt0; s_b1[r_][1] = bl1 ^ rt1;                      \
        s_b1[r_][2] = bl2 ^ rt2; s_b1[r_][3] = bl3 ^ rt3;                      \
        s_b2[r_][0] = bl0 & rt0; s_b2[r_][1] = bl1 & rt1;                      \
        s_b2[r_][2] = bl2 & rt2; s_b2[r_][3] = bl3 & rt3;                      \
        int fl_ = (((bl0 | rt0) | (bl1 | rt1) | (bl2 | rt2) | (bl3 | rt3))     \
                   == 0ull) ? 2 : 0;                                           \
        if (r_ >= 1 && r_ <= HH - 3) {                                         \
            const int sm_ = s_src[r_ - 1];                                     \
            bool inm_ = (r_ - 1 >= hmin) && (r_ - 1 <= hmax);                  \
            u64 m0 = s_n[sm_][0] | (inm_ ? rc0 : 0ull);                        \
            u64 m1 = s_n[sm_][1] | (inm_ ? rc1 : 0ull);                        \
            u64 m2 = s_n[sm_][2] | (inm_ ? rc2 : 0ull);                        \
            u64 m3 = s_n[sm_][3] | (inm_ ? rc3 : 0ull);                        \
            u64 d = (m0 ^ g0) | (m1 ^ g1) | (m2 ^ g2) | (m3 ^ g3)              \
                  | (g0 ^ n0) | (g1 ^ n1) | (g2 ^ n2) | (g3 ^ n3);             \
            fl_ |= (d == 0ull) ? 1 : 0;                                        \
        }                                                                      \
        FLOUT = fl_;                                                           \
    } while (0)

            {
                int fl;
                PHASEB_ROW(tid, fl);
                u32 f1 = __ballot_sync(FULLM, fl & 1);
                u32 f2 = __ballot_sync(FULLM, fl & 2);
                if (lane == 0) { s_fmap[warp] = f1; s_zmap[warp] = f2; }
            }
            if (tid < 96) {
                int fl;
                PHASEB_ROW(128 + tid, fl);
                u32 f1 = __ballot_sync(FULLM, fl & 1);
                u32 f2 = __ballot_sync(FULLM, fl & 2);
                if (lane == 0) { s_fmap[4 + warp] = f1; s_zmap[4 + warp] = f2; }
            }
            if (diff) s_chg[pass] = 1;   // benign multi-writer race (all write 1)
#undef PHASEB_ROW
        }
        __syncthreads();

        // converged: pass(m)==m, all remaining passes are identity
        if (!s_chg[pass]) break;   // write-once flag: no reset, no race
    }

    // ---- unpack to float: one float4 per 4 columns ----
#pragma unroll 4
    for (int idx = tid; idx < IMG / 4; idx += 128) {
        int r = idx / 56, cg = idx - r * 56;
        int col = cg * 4;                       // 4-aligned: nibble within one word
        u32 bits = (u32)(s_mask[r][col >> 6] >> (col & 63)) & 0xFu;
        float4 o;
        o.x = (bits & 1u) ? 1.0f : 0.0f;
        o.y = (bits & 2u) ? 1.0f : 0.0f;
        o.z = (bits & 4u) ? 1.0f : 0.0f;
        o.w = (bits & 8u) ? 1.0f : 0.0f;
        ((float4*)oi)[idx] = o;
    }
}

extern "C" void kernel_launch(void* const* d_in, const int* in_sizes, int n_in,
                              void* d_out, int out_size) {
    const float* x = (const float*)d_in[0];
    float* out = (float*)d_out;
    int nimg = in_sizes[0] / IMG;   // B*C = 8
    mask_ca_kernel<<<nimg, 128>>>(x, out);
}

// round 17
// speedup vs baseline: 1.2922x; 1.1456x over previous
#include <cuda_runtime.h>

typedef unsigned long long u64;
typedef unsigned int u32;

#define HH 224
#define WW 224
#define IMG (HH * WW)
#define NPASS 9
#define W3MASK 0xFFFFFFFFull
#define FULLM 0xFFFFFFFFu

// bits 0..k-1 of word j (j*64 .. j*64+63) of a 224-bit mask
__device__ __forceinline__ u64 mask_lt(int k, int j) {
    int lo = j * 64;
    if (k <= lo) return 0ull;
    if (k >= lo + 64) return ~0ull;
    return (1ull << (k - lo)) - 1ull;
}

// first row e >= q such that row e-1 is a zero-b row (z-bit set); HH if none.
// q >= 1. Segment starting at e may be initialized with (p1,p2)=(0,0): exact
// (nn(e-1)=0 forces ab(e)=0 and ab(e+1)=0).
__device__ __forceinline__ int find_entry(const u32* zm, int q) {
    int pos = q - 1;
    int w = pos >> 5;
    u32 bits = zm[w] & (FULLM << (pos & 31));
    while (bits == 0) {
        if (++w >= 7) return HH;
        bits = zm[w];
    }
    int z = (w << 5) + __ffs(bits) - 1;
    return (z + 1 > HH) ? HH : z + 1;
}

// next set bit of m[] at position >= pos (7 words); HH if none.
__device__ __forceinline__ int next_bit(const u32* m, int pos) {
    if (pos >= HH) return HH;
    int w = pos >> 5;
    u32 bits = m[w] & (FULLM << (pos & 31));
    while (bits == 0) {
        if (++w >= 7) return HH;
        bits = m[w];
    }
    return (w << 5) + __ffs(bits) - 1;
}

__global__ __launch_bounds__(128) void mask_ca_kernel(const float* __restrict__ x,
                                                      float* __restrict__ out) {
    __shared__ u64 s_mask[HH][4];     // current mask (post rect-fill)
    __shared__ u64 s_b1[HH][4];       // base == exactly one of below/right
    __shared__ u64 s_b2[HH][4];       // base == both
    __shared__ u64 s_n[HH + 2][4];    // scan output + 2 phantom rows (ones, zeros)
    __shared__ int s_src[HH + 2];     // representative row; phantoms self-map
    __shared__ u32 s_fmap[8];         // bit r: g(r-1)==g(r)==g(r+1) (=> b(r)==b(r-1))
    __shared__ u32 s_zmap[8];         // bit r: (b1|b2)==0 at row r (carry barrier!)
    __shared__ u64 s_wcm[4][4];       // per-warp column-OR of its rows
    __shared__ int s_whmin[4], s_whmax[4];
    __shared__ int s_chg[NPASS];      // write-once per pass (no reset race)

    const int tid  = threadIdx.x;
    const int lane = tid & 31;
    const int warp = tid >> 5;
    const float* xi = x + (size_t)blockIdx.x * IMG;
    float* oi = out + (size_t)blockIdx.x * IMG;

    // ---- pack input: threshold > 0.8, byte-wise, no ballots, deep MLP ----
    {
        unsigned char* sb = (unsigned char*)s_mask;
#pragma unroll 4
        for (int idx = tid; idx < HH * 32; idx += 128) {
            int r = idx >> 5, b = idx & 31;
            unsigned char v = 0;
            if (b < 28) {
                const float4* p = (const float4*)(xi + r * WW + b * 8);
                float4 a = p[0], c = p[1];
                v = (unsigned char)((a.x > 0.8f)
                  | ((a.y > 0.8f) << 1)
                  | ((a.z > 0.8f) << 2)
                  | ((a.w > 0.8f) << 3)
                  | ((c.x > 0.8f) << 4)
                  | ((c.y > 0.8f) << 5)
                  | ((c.z > 0.8f) << 6)
                  | ((c.w > 0.8f) << 7));
            }
            sb[idx] = v;
        }
    }
    if (tid == 0) {
#pragma unroll
        for (int p = 0; p < NPASS; p++) s_chg[p] = 0;
        // phantom rows for branch-free phase B:
        // row HH  = all-ones  (below-neighbor of row HH-2; rect-OR is absorbing)
        // row HH+1 = all-zero (below-neighbor of row HH-1; rect never applies)
        s_n[HH][0] = ~0ull; s_n[HH][1] = ~0ull; s_n[HH][2] = ~0ull; s_n[HH][3] = W3MASK;
        s_n[HH + 1][0] = 0ull; s_n[HH + 1][1] = 0ull;
        s_n[HH + 1][2] = 0ull; s_n[HH + 1][3] = 0ull;
        s_src[HH] = HH; s_src[HH + 1] = HH + 1;
    }
    __syncthreads();

    // ---- initial b1/b2 + flag bitmaps from packed input ----
#define INIT_ROW(RR, FLOUT) do {                                               \
        const int r_ = (RR);                                                   \
        u64 g0 = s_mask[r_][0], g1 = s_mask[r_][1];                            \
        u64 g2 = s_mask[r_][2], g3 = s_mask[r_][3];                            \
        u64 n0, n1, n2, n3;                                                    \
        if (r_ < HH - 2) {                                                     \
            n0 = s_mask[r_ + 1][0]; n1 = s_mask[r_ + 1][1];                    \
            n2 = s_mask[r_ + 1][2]; n3 = s_mask[r_ + 1][3];                    \
        } else if (r_ == HH - 2) {                                             \
            n0 = ~0ull; n1 = ~0ull; n2 = ~0ull; n3 = W3MASK;                   \
        } else { n0 = n1 = n2 = n3 = 0ull; }                                   \
        u64 bl0 = g0 & n0, bl1 = g1 & n1, bl2 = g2 & n2, bl3 = g3 & n3;        \
        u64 rt0 = ((g0 >> 1) | (g1 << 63)) & g0;                               \
        u64 rt1 = ((g1 >> 1) | (g2 << 63)) & g1;                               \
        u64 rt2 = ((g2 >> 1) | (g3 << 63)) & g2;                               \
        u64 rt3 = ((g3 >> 1) | (1ull << 30)) & g3;                             \
        s_b1[r_][0] = bl0 ^ rt0; s_b1[r_][1] = bl1 ^ rt1;                      \
        s_b1[r_][2] = bl2 ^ rt2; s_b1[r_][3] = bl3 ^ rt3;                      \
        s_b2[r_][0] = bl0 & rt0; s_b2[r_][1] = bl1 & rt1;                      \
        s_b2[r_][2] = bl2 & rt2; s_b2[r_][3] = bl3 & rt3;                      \
        int fl_ = (((bl0 | rt0) | (bl1 | rt1) | (bl2 | rt2) | (bl3 | rt3))     \
                   == 0ull) ? 2 : 0;                                           \
        if (r_ >= 1 && r_ <= HH - 3) {                                         \
            u64 m0 = s_mask[r_ - 1][0], m1 = s_mask[r_ - 1][1];                \
            u64 m2 = s_mask[r_ - 1][2], m3 = s_mask[r_ - 1][3];                \
            u64 d = (m0 ^ g0) | (m1 ^ g1) | (m2 ^ g2) | (m3 ^ g3)              \
                  | (g0 ^ n0) | (g1 ^ n1) | (g2 ^ n2) | (g3 ^ n3);             \
            fl_ |= (d == 0ull) ? 1 : 0;                                        \
        }                                                                      \
        FLOUT = fl_;                                                           \
    } while (0)

    {
        int fl;
        INIT_ROW(tid, fl);
        u32 f1 = __ballot_sync(FULLM, fl & 1);
        u32 f2 = __ballot_sync(FULLM, fl & 2);
        if (lane == 0) { s_fmap[warp] = f1; s_zmap[warp] = f2; }
    }
    if (tid < 96) {
        int fl;
        INIT_ROW(128 + tid, fl);
        u32 f1 = __ballot_sync(FULLM, fl & 1);
        u32 f2 = __ballot_sync(FULLM, fl & 2);
        if (lane == 0) { s_fmap[4 + warp] = f1; s_zmap[4 + warp] = f2; }
    }
    __syncthreads();

    for (int pass = 0; pass < NPASS; pass++) {
        // ---- serial raster recurrence, 4 warps on disjoint segments ----
        {
            const int j = lane & 3;
            const int jm = j ? (j - 1) : 0;   // word j-1 (dummy for j==0)
            const bool loTest = (lane < 16);
            const u32 grp = lane >> 2;
            const bool isChb = (grp < 2);             // lanes 0-7:  gn != gs
            const bool isE1  = (grp >= 2 && grp < 4); // lanes 8-15: nn != p1
            u32 fm[7], zm[7], em[7];
#pragma unroll
            for (int jj = 0; jj < 7; jj++) {
                fm[jj] = s_fmap[jj]; zm[jj] = s_zmap[jj]; em[jj] = fm[jj] | zm[jj];
            }
            const int entry = (warp == 0) ? 0 : find_entry(zm, 56 * warp);
            const int end   = (warp == 3) ? HH : find_entry(zm, 56 * (warp + 1));

            u64 p1 = 0ull, p2 = 0ull;
            u64 pm1 = 0ull, pm2 = 0ull;   // history of word j-1 (exact mirror)
            if (warp == 0) {
                p1 = (j < 3) ? ~0ull : W3MASK;   // virtual row -1 = ones
                pm1 = (j > 0) ? ~0ull : 0ull;     // word j-1 of row -1 (j==0 unused)
            }
            u64 cm = 0ull;
            int hmin = 1 << 30, hmax = -1;
            int e1 = 0, e2 = 0, p1z = 0, nzflag = 0, r0 = entry;
            int r = entry;
            while (r < end) {
                const int w = r >> 5, bpos = r & 31;
                if ((e1 & e2) && ((fm[w] >> bpos) & 1)) {
                    // hit RUN: consecutive rows with b(q)==b(q-1); nn stays == p1
                    int erun;
                    u32 xbits = (~fm[w]) >> bpos;
                    if (xbits) erun = r + __ffs(xbits) - 1;
                    else {
                        int ww = w + 1;
                        while (ww < 7 && fm[ww] == FULLM) ww++;
                        erun = (ww < 7) ? ww * 32 + __ffs(~fm[ww]) - 1 : HH;
                    }
                    if (erun > end) erun = end;
                    for (int q = r + lane; q < erun; q += 32) s_src[q] = r0;
                    if (nzflag) hmax = erun - 1;   // state unchanged across the run
                    r = erun;
                    continue;
                }
                if ((zm[w] >> bpos) & 1) {
                    // zero row: b1|b2==0 -> nn=0 for ANY ab (O=0 keeps seed empty)
                    if (lane < 4) s_n[r][j] = 0ull;
                    if (lane == 0) s_src[r] = r;
                    r0 = r;
                    e2 = e1; e1 = p1z; p1z = 1; nzflag = 0;
                    p2 = p1; p1 = 0ull;
                    pm2 = pm1; pm1 = 0ull;   // mirror
                    r++;
                    continue;
                }
                // ---- miss RUN: rows r .. ev-1 have no fm/zm events; tight loop
                // with no hit/zero dispatch inside (pass-1 band = one long run)
                int ev = next_bit(em, r + 1);
                if (ev > end) ev = end;
                do {
                    u64 ab  = p1 & p2;
                    u64 abm = pm1 & pm2;                      // off-chain (j>0)
                    u64 b1 = s_b1[r][j],  b2 = s_b2[r][j];
                    u64 b1m = s_b1[r][jm], b2m = s_b2[r][jm]; // latency-parallel LDS
                    u64 O = b2 | (b1 & ab);      // a>=2
                    u64 P = (b1 ^ ab) & ~b2;     // a==1
                    // word j-1 top bits computed LOCALLY (no shfl on the chain)
                    u64 Om = b2m | (b1m & abm);
                    u64 Pm = (b1m ^ abm) & ~b2m;
                    u32 sIn = (j == 0) ? 0u : (u32)(Pm >> 63);
                    u32 aIn = (j == 0) ? 1u : ((u32)(Om >> 63) & 1u);  // n(-1)=1
                    u32 cIn = (j == 0) ? 2u : ((u32)(Om >> 62) & 3u);  // n(-2)=0
                    u64 S  = P & ~((P << 1) | (u64)sIn);               // run starts
                    u64 gs = S & ((O << 1) | (u64)aIn) & ((O << 2) | (u64)cIn);
                    u64 F = 0ull, nn;
                    u32 e1n, nzn;
                    u32 gb = __ballot_sync(FULLM, gs != 0ull);
                    if (gb) {
                        // gs monotone; F pure function of gs -> iterate on gs.
                        // convergence + e1 + nz share ONE 3-way split ballot.
                        u32 bal3 = 0;
                        for (int it = 0; it < 256; it++) {
                            // 224-bit add P+gs; gen/prop share one ballot
                            u64 s = P + gs;
                            u32 bal2 = __ballot_sync(FULLM,
                                           loTest ? (s < P) : (s == ~0ull));
                            u32 gm4 = bal2 & 0xFu;           // generate
                            u32 pm4 = (bal2 >> 16) & 0xFu;   // propagate
                            u32 c1 = gm4 & 1u;
                            u32 c2 = ((gm4 >> 1) & 1u) | (((pm4 >> 1) & 1u) & c1);
                            u32 c3 = ((gm4 >> 2) & 1u) | (((pm4 >> 2) & 1u) & c2);
                            u32 cw = (c1 << 1) | (c2 << 2) | (c3 << 3);
                            u64 s2 = s + (u64)((cw >> j) & 1u);
                            F = P & ~s2;                 // filled runs
                            u64 k = O | F;
                            u32 kh  = (u32)(k >> 62) & 3u;   // [1]=k63 [0]=k62
                            u32 khp = __shfl_up_sync(FULLM, kh, 1);
                            u32 aI = (j == 0) ? 1u : ((khp >> 1) & 1u);
                            u32 cI = (j == 0) ? 2u : (khp & 3u);
                            u64 gn = S & ((k << 1) | (u64)aI) & ((k << 2) | (u64)cI);
                            nn = O | F;
                            bal3 = __ballot_sync(FULLM,
                                       isChb ? (gn != gs)
                                             : (isE1 ? ((nn ^ p1) != 0ull)
                                                     : (nn != 0ull)));
                            gs = gn;
                            if (!(bal3 & 0xFFu)) break;   // converged
                        }
                        e1n = (((bal3 >> 8) & 0xFFu) == 0u);
                        nzn = (((bal3 >> 16) & 0xFFFFu) != 0u);
                    } else {
                        nn = O;   // F = 0
                        u32 bal = __ballot_sync(FULLM,
                                      loTest ? ((nn ^ p1) != 0ull) : (nn != 0ull));
                        e1n = ((bal & 0xFu) == 0u);
                        nzn = (((bal >> 16) & 0xFu) != 0u);
                    }
                    if (lane < 4) s_n[r][j] = nn;
                    if (lane == 0) s_src[r] = r;
                    r0 = r;
                    // pm1 via shfl; result not needed until mid-next-row
                    u64 pmn = __shfl_up_sync(FULLM, nn, 1);
                    e2 = e1; e1 = (int)e1n;
                    p1z = !nzn;
                    if (nzn) {
                        if (hmax < 0) hmin = r;
                        hmax = r;
                        cm |= nn;
                        nzflag = 1;
                    } else {
                        nzflag = 0;
                    }
                    p2 = p1; p1 = nn;
                    pm2 = pm1; pm1 = pmn;
                    r++;
                } while (r < ev);
            }
            // per-warp bbox handoff (no atomics; fixed slots)
            if (lane < 4) s_wcm[warp][j] = cm;
            if (lane == 0) { s_whmin[warp] = hmin; s_whmax[warp] = hmax; }
        }
        __syncthreads();   // B1: s_n + per-warp bbox ready

        // ---- fused parallel phase: combine bbox + rect + diff + next b/flags ----
        {
            // every thread combines the 4 warp results (replicated, branch-free)
            int hmin = min(min(s_whmin[0], s_whmin[1]), min(s_whmin[2], s_whmin[3]));
            int hmax = max(max(s_whmax[0], s_whmax[1]), max(s_whmax[2], s_whmax[3]));
            u64 cm0 = s_wcm[0][0] | s_wcm[1][0] | s_wcm[2][0] | s_wcm[3][0];
            u64 cm1 = s_wcm[0][1] | s_wcm[1][1] | s_wcm[2][1] | s_wcm[3][1];
            u64 cm2 = s_wcm[0][2] | s_wcm[1][2] | s_wcm[2][2] | s_wcm[3][2];
            u64 cm3 = s_wcm[0][3] | s_wcm[1][3] | s_wcm[2][3] | s_wcm[3][3];
            int wmin, wmax;
            if (hmax < 0) {   // empty: argmax-of-all-False semantics
                hmin = 0; hmax = HH - 1; wmin = 0; wmax = WW - 1;
            } else {
                if (cm0)      wmin = __ffsll((long long)cm0) - 1;
                else if (cm1) wmin = 64  + __ffsll((long long)cm1) - 1;
                else if (cm2) wmin = 128 + __ffsll((long long)cm2) - 1;
                else          wmin = 192 + __ffsll((long long)cm3) - 1;
                if (cm3)      wmax = 255 - __clzll((long long)cm3);
                else if (cm2) wmax = 191 - __clzll((long long)cm2);
                else if (cm1) wmax = 127 - __clzll((long long)cm1);
                else          wmax = 63  - __clzll((long long)cm0);
            }
            // rect columns [wmin, wmax)  (wmax EXCLUSIVE, matching reference slice)
            const u64 rc0 = mask_lt(wmax, 0) & ~mask_lt(wmin, 0);
            const u64 rc1 = mask_lt(wmax, 1) & ~mask_lt(wmin, 1);
            const u64 rc2 = mask_lt(wmax, 2) & ~mask_lt(wmin, 2);
            const u64 rc3 = mask_lt(wmax, 3) & ~mask_lt(wmin, 3);
            u64 diff = 0;

            // branch-free row macro: below-neighbor via phantom index
            //   idxn = r+1 for r < HH-2, r+2 (-> phantom ones/zero) otherwise
#define PHASEB_ROW(RR, FLOUT) do {                                             \
        const int r_ = (RR);                                                   \
        const int sr_ = s_src[r_];                                             \
        bool in_ = (r_ >= hmin) && (r_ <= hmax);                               \
        u64 g0 = s_n[sr_][0] | (in_ ? rc0 : 0ull);                             \
        u64 g1 = s_n[sr_][1] | (in_ ? rc1 : 0ull);                             \
        u64 g2 = s_n[sr_][2] | (in_ ? rc2 : 0ull);                             \
        u64 g3 = s_n[sr_][3] | (in_ ? rc3 : 0ull);                             \
        diff |= (g0 ^ s_mask[r_][0]) | (g1 ^ s_mask[r_][1])                    \
              | (g2 ^ s_mask[r_][2]) | (g3 ^ s_mask[r_][3]);                   \
        s_mask[r_][0] = g0; s_mask[r_][1] = g1;                                \
        s_mask[r_][2] = g2; s_mask[r_][3] = g3;                                \
        const int idxn = (r_ >= HH - 2) ? (r_ + 2) : (r_ + 1);                 \
        const int sn_ = s_src[idxn];                                           \
        bool in1_ = (r_ + 1 >= hmin) && (r_ + 1 <= hmax);                      \
        u64 n0 = s_n[sn_][0] | (in1_ ? rc0 : 0ull);                            \
        u64 n1 = s_n[sn_][1] | (in1_ ? rc1 : 0ull);                            \
        u64 n2 = s_n[sn_][2] | (in1_ ? rc2 : 0ull);                            \
        u64 n3 = s_n[sn_][3] | (in1_ ? rc3 : 0ull);                            \
        u64 bl0 = g0 & n0, bl1 = g1 & n1, bl2 = g2 & n2, bl3 = g3 & n3;        \
        u64 rt0 = ((g0 >> 1) | (g1 << 63)) & g0;                               \
        u64 rt1 = ((g1 >> 1) | (g2 << 63)) & g1;                               \
        u64 rt2 = ((g2 >> 1) | (g3 << 63)) & g2;                               \
        u64 rt3 = ((g3 >> 1) | (1ull << 30)) & g3;                             \
        s_b1[r_][0] = bl0 ^ rt0; s_b1[r_][1] = bl1 ^ rt1;                      \
        s_b1[r_][2] = bl2 ^ rt2; s_b1[r_][3] = bl3 ^ rt3;                      \
        s_b2[r_][0] = bl0 & rt0; s_b2[r_][1] = bl1 & rt1;                      \
        s_b2[r_][2] = bl2 & rt2; s_b2[r_][3] = bl3 & rt3;                      \
        int fl_ = (((bl0 | rt0) | (bl1 | rt1) | (bl2 | rt2) | (bl3 | rt3))     \
                   == 0ull) ? 2 : 0;                                           \
        const int idxm = (r_ > 0) ? (r_ - 1) : 0;                              \
        const int sm_ = s_src[idxm];                                           \
        bool inm_ = (idxm >= hmin) && (idxm <= hmax);                          \
        u64 m0 = s_n[sm_][0] | (inm_ ? rc0 : 0ull);                            \
        u64 m1 = s_n[sm_][1] | (inm_ ? rc1 : 0ull);                            \
        u64 m2 = s_n[sm_][2] | (inm_ ? rc2 : 0ull);                            \
        u64 m3 = s_n[sm_][3] | (inm_ ? rc3 : 0ull);                            \
        u64 d = (m0 ^ g0) | (m1 ^ g1) | (m2 ^ g2) | (m3 ^ g3)                  \
              | (g0 ^ n0) | (g1 ^ n1) | (g2 ^ n2) | (g3 ^ n3);                 \
        fl_ |= (int)((d == 0ull) & (r_ >= 1) & (r_ <= HH - 3));                \
        FLOUT = fl_;                                                           \
    } while (0)

            {
                int fl;
                PHASEB_ROW(tid, fl);
                u32 f1 = __ballot_sync(FULLM, fl & 1);
                u32 f2 = __ballot_sync(FULLM, fl & 2);
                if (lane == 0) { s_fmap[warp] = f1; s_zmap[warp] = f2; }
            }
            if (tid < 96) {
                int fl;
                PHASEB_ROW(128 + tid, fl);
                u32 f1 = __ballot_sync(FULLM, fl & 1);
                u32 f2 = __ballot_sync(FULLM, fl & 2);
                if (lane == 0) { s_fmap[4 + warp] = f1; s_zmap[4 + warp] = f2; }
            }
            if (diff) s_chg[pass] = 1;   // benign multi-writer race (all write 1)
#undef PHASEB_ROW
        }
        __syncthreads();

        // converged: pass(m)==m, all remaining passes are identity
        if (!s_chg[pass]) break;   // write-once flag: no reset, no race
    }

    // ---- unpack to float: one float4 per 4 columns ----
#pragma unroll 4
    for (int idx = tid; idx < IMG / 4; idx += 128) {
        int r = idx / 56, cg = idx - r * 56;
        int col = cg * 4;                       // 4-aligned: nibble within one word
        u32 bits = (u32)(s_mask[r][col >> 6] >> (col & 63)) & 0xFu;
        float4 o;
        o.x = (bits & 1u) ? 1.0f : 0.0f;
        o.y = (bits & 2u) ? 1.0f : 0.0f;
        o.z = (bits & 4u) ? 1.0f : 0.0f;
        o.w = (bits & 8u) ? 1.0f : 0.0f;
        ((float4*)oi)[idx] = o;
    }
}

extern "C" void kernel_launch(void* const* d_in, const int* in_sizes, int n_in,
                              void* d_out, int out_size) {
    const float* x = (const float*)d_in[0];
    float* out = (float*)d_out;
    int nimg = in_sizes[0] / IMG;   // B*C = 8
    mask_ca_kernel<<<nimg, 128>>>(x, out);
}